// round 1
// baseline (speedup 1.0000x reference)
#include <cuda_runtime.h>
#include <math_constants.h>

// Problem shape (fixed by the dataset)
#define NB 8
#define NQ 2048
#define NKS 2048   // key sequence length
#define ND 1024

// Scratch: exp'd scores E[b][q][k] (128 MiB) and per-column reciprocal sums.
__device__ float g_E[(size_t)NB * NQ * NKS];
__device__ float g_recipS[NB * NKS];

// ---------------------------------------------------------------------------
// Kernel A: S[b] = Q[b] (NQ x ND) @ K[b]^T (ND x NKS)   (both operands K-major)
// Classic 128x128x16 tile, 256 threads, 8x8 microtile, transposed smem.
// ---------------------------------------------------------------------------
__global__ __launch_bounds__(256) void qk_gemm(const float* __restrict__ Qm,
                                               const float* __restrict__ Km) {
    __shared__ float As[16][128];
    __shared__ float Bs[16][128];

    const int b = blockIdx.z;
    const float* A  = Qm + (size_t)b * NQ * ND + (size_t)blockIdx.y * 128 * ND;
    const float* Bm = Km + (size_t)b * NKS * ND + (size_t)blockIdx.x * 128 * ND;
    float* C = g_E + (size_t)b * NQ * NKS + (size_t)blockIdx.y * 128 * NKS
                   + (size_t)blockIdx.x * 128;

    const int tid = threadIdx.x;
    const int tx = tid & 15;   // column group (k)
    const int ty = tid >> 4;   // row group (q)

    float acc[8][8];
#pragma unroll
    for (int i = 0; i < 8; i++)
#pragma unroll
        for (int j = 0; j < 8; j++) acc[i][j] = 0.f;

    for (int kt = 0; kt < ND; kt += 16) {
#pragma unroll
        for (int l = 0; l < 2; l++) {
            int idx = tid + l * 256;       // 0..511 float4 slots
            int row = idx >> 2;            // 0..127
            int cv  = (idx & 3) * 4;       // 0,4,8,12
            float4 va = *(const float4*)(A  + (size_t)row * ND + kt + cv);
            As[cv + 0][row] = va.x; As[cv + 1][row] = va.y;
            As[cv + 2][row] = va.z; As[cv + 3][row] = va.w;
            float4 vb = *(const float4*)(Bm + (size_t)row * ND + kt + cv);
            Bs[cv + 0][row] = vb.x; Bs[cv + 1][row] = vb.y;
            Bs[cv + 2][row] = vb.z; Bs[cv + 3][row] = vb.w;
        }
        __syncthreads();

#pragma unroll
        for (int d = 0; d < 16; d++) {
            float a[8], bb[8];
            *(float4*)(a)      = *(const float4*)&As[d][ty * 8];
            *(float4*)(a + 4)  = *(const float4*)&As[d][ty * 8 + 4];
            *(float4*)(bb)     = *(const float4*)&Bs[d][tx * 8];
            *(float4*)(bb + 4) = *(const float4*)&Bs[d][tx * 8 + 4];
#pragma unroll
            for (int i = 0; i < 8; i++)
#pragma unroll
                for (int j = 0; j < 8; j++) acc[i][j] = fmaf(a[i], bb[j], acc[i][j]);
        }
        __syncthreads();
    }

#pragma unroll
    for (int i = 0; i < 8; i++) {
        float* crow = C + (size_t)(ty * 8 + i) * NKS + tx * 8;
        *(float4*)(crow)     = make_float4(acc[i][0], acc[i][1], acc[i][2], acc[i][3]);
        *(float4*)(crow + 4) = make_float4(acc[i][4], acc[i][5], acc[i][6], acc[i][7]);
    }
}

// ---------------------------------------------------------------------------
// Kernel B: column softmax (over q, per fixed k).
// Block handles 32 columns; 8 row-groups of 32 threads each. Writes
// E = exp(S - m) in place and 1/sum per column (normalization folded into PV).
// ---------------------------------------------------------------------------
__global__ __launch_bounds__(256) void col_softmax() {
    const int blk = blockIdx.x;
    const int b = blk / (NKS / 32);
    const int kbase = (blk % (NKS / 32)) * 32;
    const int tid = threadIdx.x;
    const int c  = tid & 31;   // column within group of 32
    const int rg = tid >> 5;   // row group 0..7

    float* S = g_E + (size_t)b * NQ * NKS + kbase;
    __shared__ float red[8][32];

    // Phase 1: column max over q
    float m = -CUDART_INF_F;
    for (int q = rg; q < NQ; q += 8) m = fmaxf(m, S[(size_t)q * NKS + c]);
    red[rg][c] = m;
    __syncthreads();
    if (rg == 0) {
        float mm = red[0][c];
#pragma unroll
        for (int r = 1; r < 8; r++) mm = fmaxf(mm, red[r][c]);
        red[0][c] = mm;
    }
    __syncthreads();
    m = red[0][c];
    __syncthreads();

    // Phase 2: exp + write-back + partial sums
    float sum = 0.f;
    for (int q = rg; q < NQ; q += 8) {
        size_t off = (size_t)q * NKS + c;
        float e = __expf(S[off] - m);
        S[off] = e;
        sum += e;
    }
    red[rg][c] = sum;
    __syncthreads();
    if (rg == 0) {
        float s = 0.f;
#pragma unroll
        for (int r = 0; r < 8; r++) s += red[r][c];
        g_recipS[b * NKS + kbase + c] = 1.0f / s;
    }
}

// ---------------------------------------------------------------------------
// Kernel C: out[b] = E[b] (NQ x NKS) @ diag(1/S) @ V[b] (NKS x ND)
// NN GEMM; the 1/sum scaling is applied while loading V tiles.
// ---------------------------------------------------------------------------
__global__ __launch_bounds__(256) void pv_gemm(const float* __restrict__ Vm,
                                               float* __restrict__ Out) {
    __shared__ float As[16][128];   // E tile, transposed: [k][q]
    __shared__ float Bs[16][128];   // V tile: [k][d]

    const int b = blockIdx.z;
    const float* A  = g_E + (size_t)b * NQ * NKS + (size_t)blockIdx.y * 128 * NKS;
    const float* Bm = Vm  + (size_t)b * NKS * ND + (size_t)blockIdx.x * 128;
    const float* rS = g_recipS + b * NKS;
    float* C = Out + (size_t)b * NQ * ND + (size_t)blockIdx.y * 128 * ND
                   + (size_t)blockIdx.x * 128;

    const int tid = threadIdx.x;
    const int tx = tid & 15;
    const int ty = tid >> 4;

    float acc[8][8];
#pragma unroll
    for (int i = 0; i < 8; i++)
#pragma unroll
        for (int j = 0; j < 8; j++) acc[i][j] = 0.f;

    for (int kt = 0; kt < NKS; kt += 16) {
#pragma unroll
        for (int l = 0; l < 2; l++) {
            int idx = tid + l * 256;       // 0..511
            // E tile: 128 rows (q) x 16 cols (k) -> transpose into As
            int row = idx >> 2;
            int cv  = (idx & 3) * 4;
            float4 va = *(const float4*)(A + (size_t)row * NKS + kt + cv);
            As[cv + 0][row] = va.x; As[cv + 1][row] = va.y;
            As[cv + 2][row] = va.z; As[cv + 3][row] = va.w;
            // V tile: 16 rows (k) x 128 cols (d), scaled by 1/sum(k)
            int r2 = idx >> 5;             // 0..15
            int c2 = (idx & 31) * 4;       // 0..124
            float4 vb = *(const float4*)(Bm + (size_t)(kt + r2) * ND + c2);
            float sc = rS[kt + r2];
            float4 vs = make_float4(vb.x * sc, vb.y * sc, vb.z * sc, vb.w * sc);
            *(float4*)&Bs[r2][c2] = vs;
        }
        __syncthreads();

#pragma unroll
        for (int k = 0; k < 16; k++) {
            float a[8], bb[8];
            *(float4*)(a)      = *(const float4*)&As[k][ty * 8];
            *(float4*)(a + 4)  = *(const float4*)&As[k][ty * 8 + 4];
            *(float4*)(bb)     = *(const float4*)&Bs[k][tx * 8];
            *(float4*)(bb + 4) = *(const float4*)&Bs[k][tx * 8 + 4];
#pragma unroll
            for (int i = 0; i < 8; i++)
#pragma unroll
                for (int j = 0; j < 8; j++) acc[i][j] = fmaf(a[i], bb[j], acc[i][j]);
        }
        __syncthreads();
    }

#pragma unroll
    for (int i = 0; i < 8; i++) {
        float* crow = C + (size_t)(ty * 8 + i) * ND + tx * 8;
        *(float4*)(crow)     = make_float4(acc[i][0], acc[i][1], acc[i][2], acc[i][3]);
        *(float4*)(crow + 4) = make_float4(acc[i][4], acc[i][5], acc[i][6], acc[i][7]);
    }
}

extern "C" void kernel_launch(void* const* d_in, const int* in_sizes, int n_in,
                              void* d_out, int out_size) {
    const float* Qm = (const float*)d_in[0];
    const float* Km = (const float*)d_in[1];
    const float* Vm = (const float*)d_in[2];
    float* Out = (float*)d_out;

    dim3 gA(NKS / 128, NQ / 128, NB);   // 16 x 16 x 8
    qk_gemm<<<gA, 256>>>(Qm, Km);

    col_softmax<<<NB * (NKS / 32), 256>>>();

    dim3 gC(ND / 128, NQ / 128, NB);    // 8 x 16 x 8
    pv_gemm<<<gC, 256>>>(Vm, Out);
}

// round 3
// speedup vs baseline: 2.0297x; 2.0297x over previous
#include <cuda_runtime.h>
#include <cuda_bf16.h>
#include <math_constants.h>
#include <cstdint>

#define NB 8
#define NQ 2048
#define NK 2048
#define ND 1024

// ---------------------------------------------------------------------------
// Scratch (device globals; no allocations allowed)
// Q' rows: [Qhi | Qhi | Qlo]  pitch 3072
// K' rows: [Khi | Klo | Khi]  pitch 3072
// V^T' rows (d-major): [Vhi^T | Vlo^T | Vhi^T] pitch 6144
// E' rows: [Ehi | Ehi | Elo] pitch 6144  (E pre-normalized by column sum)
// ---------------------------------------------------------------------------
__device__ __nv_bfloat16 gQp[(size_t)NB * NQ * 3072];
__device__ __nv_bfloat16 gKp[(size_t)NB * NK * 3072];
__device__ __nv_bfloat16 gVT[(size_t)NB * ND * 6144];
__device__ __nv_bfloat16 gEp[(size_t)NB * NQ * 6144];
__device__ float gS[(size_t)NB * NQ * NK];

// ---------------------------------------------------------------------------
__device__ __forceinline__ uint32_t smem_u32(const void* p) {
    uint32_t a;
    asm("{ .reg .u64 t; cvta.to.shared.u64 t, %1; cvt.u32.u64 %0, t; }"
        : "=r"(a) : "l"(p));
    return a;
}

#define CP_ASYNC16(dst, src) \
    asm volatile("cp.async.cg.shared.global [%0], [%1], 16;" :: "r"(dst), "l"(src))
#define CP_COMMIT() asm volatile("cp.async.commit_group;" ::: "memory")
#define CP_WAIT1()  asm volatile("cp.async.wait_group 1;" ::: "memory")

#define LDSM_X4(r0, r1, r2, r3, addr) \
    asm volatile("ldmatrix.sync.aligned.m8n8.x4.shared.b16 {%0,%1,%2,%3}, [%4];" \
                 : "=r"(r0), "=r"(r1), "=r"(r2), "=r"(r3) : "r"(addr))

#define MMA16816(d, a, b) \
    asm volatile("mma.sync.aligned.m16n8k16.row.col.f32.bf16.bf16.f32 " \
                 "{%0,%1,%2,%3}, {%4,%5,%6,%7}, {%8,%9}, {%0,%1,%2,%3};" \
                 : "+f"((d)[0]), "+f"((d)[1]), "+f"((d)[2]), "+f"((d)[3]) \
                 : "r"((a)[0]), "r"((a)[1]), "r"((a)[2]), "r"((a)[3]), \
                   "r"((b)[0]), "r"((b)[1]))

// ---------------------------------------------------------------------------
// Prep 1: split Q and K into bf16 hi/lo with the 3x-K concat layout
// ---------------------------------------------------------------------------
__global__ __launch_bounds__(256) void split_qk(const float* __restrict__ Qm,
                                                const float* __restrict__ Km) {
    const int row = blockIdx.x;
    const int isK = blockIdx.y;
    const float* src = (isK ? Km : Qm) + (size_t)row * ND;
    __nv_bfloat16* dst = (isK ? gKp : gQp) + (size_t)row * 3072;

    const int c = threadIdx.x * 4;
    float4 v = *(const float4*)(src + c);
    float f[4] = {v.x, v.y, v.z, v.w};
    __nv_bfloat16 hi[4], lo[4];
#pragma unroll
    for (int i = 0; i < 4; i++) {
        hi[i] = __float2bfloat16_rn(f[i]);
        lo[i] = __float2bfloat16_rn(f[i] - __bfloat162float(hi[i]));
    }
    __nv_bfloat162* d0 = (__nv_bfloat162*)(dst + c);
    d0[0] = __nv_bfloat162(hi[0], hi[1]);
    d0[1] = __nv_bfloat162(hi[2], hi[3]);
    __nv_bfloat162* d1 = (__nv_bfloat162*)(dst + 1024 + c);
    __nv_bfloat162* d2 = (__nv_bfloat162*)(dst + 2048 + c);
    if (isK) {
        d1[0] = __nv_bfloat162(lo[0], lo[1]);
        d1[1] = __nv_bfloat162(lo[2], lo[3]);
        d2[0] = __nv_bfloat162(hi[0], hi[1]);
        d2[1] = __nv_bfloat162(hi[2], hi[3]);
    } else {
        d1[0] = __nv_bfloat162(hi[0], hi[1]);
        d1[1] = __nv_bfloat162(hi[2], hi[3]);
        d2[0] = __nv_bfloat162(lo[0], lo[1]);
        d2[1] = __nv_bfloat162(lo[2], lo[3]);
    }
}

// ---------------------------------------------------------------------------
// Prep 2: transpose V (k,d)->(d,k) and split: VT' rows = [hi | lo | hi]
// ---------------------------------------------------------------------------
__global__ __launch_bounds__(256) void transpose_v(const float* __restrict__ Vm) {
    __shared__ float t[32][33];
    const int b = blockIdx.z;
    const int d0 = blockIdx.x * 32;
    const int k0 = blockIdx.y * 32;
    const int tx = threadIdx.x & 31;
    const int ty = threadIdx.x >> 5;

    const float* src = Vm + (size_t)b * NK * ND;
#pragma unroll
    for (int i = 0; i < 4; i++)
        t[ty + i * 8][tx] = src[(size_t)(k0 + ty + i * 8) * ND + d0 + tx];
    __syncthreads();

    __nv_bfloat16* dst = gVT + (size_t)b * ND * 6144;
#pragma unroll
    for (int i = 0; i < 4; i++) {
        int dd = ty + i * 8;
        float x = t[tx][dd];
        __nv_bfloat16 hi = __float2bfloat16_rn(x);
        __nv_bfloat16 lo = __float2bfloat16_rn(x - __bfloat162float(hi));
        __nv_bfloat16* r = dst + (size_t)(d0 + dd) * 6144 + k0 + tx;
        r[0]    = hi;
        r[2048] = lo;
        r[4096] = hi;
    }
}

// ---------------------------------------------------------------------------
// bf16 warp-MMA GEMM: C(tile 128x128) = A(M,K') @ B(N,K')^T, fp32 accum.
// 256 threads, 8 warps (4 M x 2 N), warp tile 32x64, BK=32, 3-stage cp.async.
// Smem rows padded to 80B -> conflict-free ldmatrix.
// ---------------------------------------------------------------------------
#define PITCH 80
#define STAGE_BYTES (2 * 128 * PITCH)   // A + B per stage = 20480

__global__ __launch_bounds__(256, 2) void tc_gemm(
    const __nv_bfloat16* __restrict__ A, const __nv_bfloat16* __restrict__ B,
    float* __restrict__ C, int lda, int ldb, int ldc, int nchunk,
    size_t sA, size_t sB, size_t sC) {
    extern __shared__ char dsmem[];

    const int tid = threadIdx.x;
    const int wid = tid >> 5;
    const int lane = tid & 31;
    const int warp_m = wid & 3;        // 0..3 -> 32-row slab
    const int warp_n = wid >> 2;       // 0..1 -> 64-col slab
    const int b = blockIdx.z;

    const __nv_bfloat16* Ag = A + b * sA + (size_t)blockIdx.y * 128 * lda;
    const __nv_bfloat16* Bg = B + b * sB + (size_t)blockIdx.x * 128 * ldb;
    float* Cg = C + b * sC + (size_t)blockIdx.y * 128 * ldc + (size_t)blockIdx.x * 128;

    const uint32_t sbase = smem_u32(dsmem);

    // cp.async mapping: 2 passes of (row = tid>>2, granule = tid&3)
    const int gr = tid & 3;
    const int r0 = tid >> 2;           // 0..63

    float acc[2][8][4];
#pragma unroll
    for (int mt = 0; mt < 2; mt++)
#pragma unroll
        for (int nt = 0; nt < 8; nt++)
#pragma unroll
            for (int i = 0; i < 4; i++) acc[mt][nt][i] = 0.f;

    auto load_chunk = [&](int c, int stage) {
        uint32_t sa = sbase + stage * STAGE_BYTES;
        uint32_t sb = sa + 128 * PITCH;
        const __nv_bfloat16* As = Ag + c * 32;
        const __nv_bfloat16* Bs = Bg + c * 32;
#pragma unroll
        for (int p = 0; p < 2; p++) {
            int row = r0 + p * 64;
            uint32_t off = (uint32_t)row * PITCH + gr * 16u;
            CP_ASYNC16(sa + off, As + (size_t)row * lda + gr * 8);
            CP_ASYNC16(sb + off, Bs + (size_t)row * ldb + gr * 8);
        }
    };

    load_chunk(0, 0); CP_COMMIT();
    load_chunk(1, 1); CP_COMMIT();

    const int lrow = lane & 15;        // ldmatrix row within 16
    const int lcol = (lane >> 4) * 16; // 0 or 16 bytes (k8..15 half)

    for (int c = 0; c < nchunk; ++c) {
        CP_WAIT1();
        __syncthreads();
        if (c + 2 < nchunk) load_chunk(c + 2, (c + 2) % 3);
        CP_COMMIT();

        const int s = c % 3;
        uint32_t sa = sbase + s * STAGE_BYTES;
        uint32_t sb = sa + 128 * PITCH;

#pragma unroll
        for (int ks = 0; ks < 2; ks++) {
            uint32_t afrag[2][4];
#pragma unroll
            for (int mt = 0; mt < 2; mt++) {
                uint32_t addr = sa + (uint32_t)(warp_m * 32 + mt * 16 + lrow) * PITCH
                              + ks * 32 + lcol;
                LDSM_X4(afrag[mt][0], afrag[mt][1], afrag[mt][2], afrag[mt][3], addr);
            }
            uint32_t bfrag[8][2];
#pragma unroll
            for (int nq = 0; nq < 4; nq++) {
                uint32_t t0, t1, t2, t3;
                uint32_t addr = sb + (uint32_t)(warp_n * 64 + nq * 16 + lrow) * PITCH
                              + ks * 32 + lcol;
                LDSM_X4(t0, t1, t2, t3, addr);
                bfrag[nq * 2 + 0][0] = t0; bfrag[nq * 2 + 0][1] = t2;
                bfrag[nq * 2 + 1][0] = t1; bfrag[nq * 2 + 1][1] = t3;
            }
#pragma unroll
            for (int mt = 0; mt < 2; mt++)
#pragma unroll
                for (int nt = 0; nt < 8; nt++)
                    MMA16816(acc[mt][nt], afrag[mt], bfrag[nt]);
        }
        __syncthreads();
    }

    // epilogue: direct global stores (float2 per fragment row)
    const int crow = lane >> 2;
    const int ccol = (lane & 3) * 2;
#pragma unroll
    for (int mt = 0; mt < 2; mt++) {
#pragma unroll
        for (int nt = 0; nt < 8; nt++) {
            float* p = Cg + (size_t)(warp_m * 32 + mt * 16 + crow) * ldc
                         + warp_n * 64 + nt * 8 + ccol;
            *(float2*)p = make_float2(acc[mt][nt][0], acc[mt][nt][1]);
            *(float2*)(p + 8 * ldc) = make_float2(acc[mt][nt][2], acc[mt][nt][3]);
        }
    }
}

// ---------------------------------------------------------------------------
// Column softmax over q (per fixed k), normalized, written as E' hi/lo splits.
// ---------------------------------------------------------------------------
__global__ __launch_bounds__(256) void col_softmax() {
    const int blk = blockIdx.x;
    const int b = blk / (NK / 32);
    const int kbase = (blk % (NK / 32)) * 32;
    const int tid = threadIdx.x;
    const int c = tid & 31;
    const int rg = tid >> 5;

    const float* S = gS + (size_t)b * NQ * NK + kbase;
    __nv_bfloat16* E = gEp + (size_t)b * NQ * 6144 + kbase;
    __shared__ float red[8][32];

    float m = -CUDART_INF_F;
    for (int q = rg; q < NQ; q += 8) m = fmaxf(m, S[(size_t)q * NK + c]);
    red[rg][c] = m;
    __syncthreads();
    if (rg == 0) {
        float mm = red[0][c];
#pragma unroll
        for (int r = 1; r < 8; r++) mm = fmaxf(mm, red[r][c]);
        red[0][c] = mm;
    }
    __syncthreads();
    m = red[0][c];
    __syncthreads();

    float sum = 0.f;
    for (int q = rg; q < NQ; q += 8) sum += __expf(S[(size_t)q * NK + c] - m);
    red[rg][c] = sum;
    __syncthreads();
    if (rg == 0) {
        float s = 0.f;
#pragma unroll
        for (int r = 0; r < 8; r++) s += red[r][c];
        red[0][c] = 1.0f / s;
    }
    __syncthreads();
    const float recip = red[0][c];

    for (int q = rg; q < NQ; q += 8) {
        float e = __expf(S[(size_t)q * NK + c] - m) * recip;
        __nv_bfloat16 hi = __float2bfloat16_rn(e);
        __nv_bfloat16 lo = __float2bfloat16_rn(e - __bfloat162float(hi));
        __nv_bfloat16* r = E + (size_t)q * 6144;
        r[c]        = hi;
        r[2048 + c] = hi;
        r[4096 + c] = lo;
    }
}

// ---------------------------------------------------------------------------
extern "C" void kernel_launch(void* const* d_in, const int* in_sizes, int n_in,
                              void* d_out, int out_size) {
    const float* Qm = (const float*)d_in[0];
    const float* Km = (const float*)d_in[1];
    const float* Vm = (const float*)d_in[2];
    float* Out = (float*)d_out;

    void *pQ, *pK, *pV, *pE, *pS;
    cudaGetSymbolAddress(&pQ, gQp);
    cudaGetSymbolAddress(&pK, gKp);
    cudaGetSymbolAddress(&pV, gVT);
    cudaGetSymbolAddress(&pE, gEp);
    cudaGetSymbolAddress(&pS, gS);

    const int SMEM = 3 * STAGE_BYTES;   // 61440
    static bool attr_done = false;
    if (!attr_done) {
        cudaFuncSetAttribute(tc_gemm, cudaFuncAttributeMaxDynamicSharedMemorySize, SMEM);
        attr_done = true;
    }

    split_qk<<<dim3(NB * NQ, 2), 256>>>(Qm, Km);
    transpose_v<<<dim3(ND / 32, NK / 32, NB), 256>>>(Vm);

    // S = Q' @ K'^T  (K' = 3072)
    tc_gemm<<<dim3(NK / 128, NQ / 128, NB), 256, SMEM>>>(
        (const __nv_bfloat16*)pQ, (const __nv_bfloat16*)pK, (float*)pS,
        3072, 3072, NK, 3072 / 32,
        (size_t)NQ * 3072, (size_t)NK * 3072, (size_t)NQ * NK);

    col_softmax<<<NB * (NK / 32), 256>>>();

    // Out = E' @ VT'^T  (K' = 6144)
    tc_gemm<<<dim3(ND / 128, NQ / 128, NB), 256, SMEM>>>(
        (const __nv_bfloat16*)pE, (const __nv_bfloat16*)pV, Out,
        6144, 6144, ND, 6144 / 32,
        (size_t)NQ * 6144, (size_t)ND * 6144, (size_t)NQ * ND);
}

// round 4
// speedup vs baseline: 2.0802x; 1.0248x over previous
#include <cuda_runtime.h>
#include <cuda_bf16.h>
#include <math_constants.h>
#include <cstdint>

#define NB 8
#define NQ 2048
#define NK 2048
#define ND 1024

// ---------------------------------------------------------------------------
// Scratch (device globals)
// Q' rows: [Qhi | Qlo]   pitch 2048
// K' rows: [Khi | Klo]   pitch 2048
// V^T' rows (d-major, recip-scaled): [Vhi | Vlo] pitch 4096
// E' rows (unnormalized exp): [Ehi | Elo] pitch 4096
// ---------------------------------------------------------------------------
__device__ __nv_bfloat16 gQp[(size_t)NB * NQ * 2048];
__device__ __nv_bfloat16 gKp[(size_t)NB * NK * 2048];
__device__ __nv_bfloat16 gVT[(size_t)NB * ND * 4096];
__device__ __nv_bfloat16 gEp[(size_t)NB * NQ * 4096];
__device__ float gS[(size_t)NB * NQ * NK];
__device__ unsigned gMax[NB * NK];
__device__ float gRecip[NB * NK];

// ---------------------------------------------------------------------------
__device__ __forceinline__ uint32_t smem_u32(const void* p) {
    uint32_t a;
    asm("{ .reg .u64 t; cvta.to.shared.u64 t, %1; cvt.u32.u64 %0, t; }"
        : "=r"(a) : "l"(p));
    return a;
}

#define CP_ASYNC16(dst, src) \
    asm volatile("cp.async.cg.shared.global [%0], [%1], 16;" :: "r"(dst), "l"(src))
#define CP_COMMIT() asm volatile("cp.async.commit_group;" ::: "memory")
#define CP_WAIT2()  asm volatile("cp.async.wait_group 2;" ::: "memory")

#define LDSM_X4(r0, r1, r2, r3, addr) \
    asm volatile("ldmatrix.sync.aligned.m8n8.x4.shared.b16 {%0,%1,%2,%3}, [%4];" \
                 : "=r"(r0), "=r"(r1), "=r"(r2), "=r"(r3) : "r"(addr))

#define MMA16816(d, a, b) \
    asm volatile("mma.sync.aligned.m16n8k16.row.col.f32.bf16.bf16.f32 " \
                 "{%0,%1,%2,%3}, {%4,%5,%6,%7}, {%8,%9}, {%0,%1,%2,%3};" \
                 : "+f"((d)[0]), "+f"((d)[1]), "+f"((d)[2]), "+f"((d)[3]) \
                 : "r"((a)[0]), "r"((a)[1]), "r"((a)[2]), "r"((a)[3]), \
                   "r"((b)[0]), "r"((b)[1]))

// Monotonic float<->uint mapping for atomicMax on signed floats
__device__ __forceinline__ unsigned fmax_flip(float f) {
    unsigned u = __float_as_uint(f);
    return (u & 0x80000000u) ? ~u : (u | 0x80000000u);
}
__device__ __forceinline__ float fmax_unflip(unsigned u) {
    return (u & 0x80000000u) ? __uint_as_float(u ^ 0x80000000u)
                             : __uint_as_float(~u);
}

// ---------------------------------------------------------------------------
// Prep: split Q and K into bf16 [hi|lo], pitch 2048. Also zeroes gMax.
// ---------------------------------------------------------------------------
__global__ __launch_bounds__(256) void split_qk(const float* __restrict__ Qm,
                                                const float* __restrict__ Km) {
    const int row = blockIdx.x;
    const int isK = blockIdx.y;
    if (!isK && row < 64) gMax[row * 256 + threadIdx.x] = 0u;   // NB*NK = 16384

    const float* src = (isK ? Km : Qm) + (size_t)row * ND;
    __nv_bfloat16* dst = (isK ? gKp : gQp) + (size_t)row * 2048;

    const int c = threadIdx.x * 4;
    float4 v = *(const float4*)(src + c);
    float f[4] = {v.x, v.y, v.z, v.w};
    __nv_bfloat16 hi[4], lo[4];
#pragma unroll
    for (int i = 0; i < 4; i++) {
        hi[i] = __float2bfloat16_rn(f[i]);
        lo[i] = __float2bfloat16_rn(f[i] - __bfloat162float(hi[i]));
    }
    __nv_bfloat162* dh = (__nv_bfloat162*)(dst + c);
    dh[0] = __nv_bfloat162(hi[0], hi[1]);
    dh[1] = __nv_bfloat162(hi[2], hi[3]);
    __nv_bfloat162* dl = (__nv_bfloat162*)(dst + 1024 + c);
    dl[0] = __nv_bfloat162(lo[0], lo[1]);
    dl[1] = __nv_bfloat162(lo[2], lo[3]);
}

// ---------------------------------------------------------------------------
// Transpose V (k,d)->(d,k), scale rows by recip[k], split hi/lo (pitch 4096).
// Runs AFTER softmax (needs gRecip).
// ---------------------------------------------------------------------------
__global__ __launch_bounds__(256) void transpose_v(const float* __restrict__ Vm) {
    __shared__ float t[32][33];
    const int b = blockIdx.z;
    const int d0 = blockIdx.x * 32;
    const int k0 = blockIdx.y * 32;
    const int tx = threadIdx.x & 31;
    const int ty = threadIdx.x >> 5;

    const float* src = Vm + (size_t)b * NK * ND;
#pragma unroll
    for (int i = 0; i < 4; i++) {
        int kk = k0 + ty + i * 8;
        t[ty + i * 8][tx] = src[(size_t)kk * ND + d0 + tx] * gRecip[b * NK + kk];
    }
    __syncthreads();

    __nv_bfloat16* dst = gVT + (size_t)b * ND * 4096;
#pragma unroll
    for (int i = 0; i < 4; i++) {
        int dd = ty + i * 8;
        float x = t[tx][dd];
        __nv_bfloat16 hi = __float2bfloat16_rn(x);
        __nv_bfloat16 lo = __float2bfloat16_rn(x - __bfloat162float(hi));
        __nv_bfloat16* r = dst + (size_t)(d0 + dd) * 4096 + k0 + tx;
        r[0]    = hi;
        r[2048] = lo;
    }
}

// ---------------------------------------------------------------------------
// bf16 warp-MMA GEMM with 3-phase hi/lo emulation walk:
//   phase0: A hi, B hi   phase1: A hi, B lo   phase2: A lo, B hi
// 256 threads, 8 warps (4Mx2N), warp tile 32x64, BK=32, 4-stage cp.async.
// Optional per-column max reduction into maxArr (flipped-uint atomicMax).
// ---------------------------------------------------------------------------
#define PITCH 80
#define STAGE_BYTES (2 * 128 * PITCH)   // 20480

__global__ __launch_bounds__(256, 2) void tc_gemm(
    const __nv_bfloat16* __restrict__ A, const __nv_bfloat16* __restrict__ B,
    float* __restrict__ C, int lda, int ldb, int ldc, int pchunks,
    size_t sA, size_t sB, size_t sC, unsigned* maxArr) {
    extern __shared__ char dsmem[];

    const int tid = threadIdx.x;
    const int wid = tid >> 5;
    const int lane = tid & 31;
    const int warp_m = wid & 3;
    const int warp_n = wid >> 2;
    const int b = blockIdx.z;
    const int nchunk = 3 * pchunks;

    const __nv_bfloat16* Ag = A + b * sA + (size_t)blockIdx.y * 128 * lda;
    const __nv_bfloat16* Bg = B + b * sB + (size_t)blockIdx.x * 128 * ldb;
    float* Cg = C + b * sC + (size_t)blockIdx.y * 128 * ldc + (size_t)blockIdx.x * 128;

    const uint32_t sbase = smem_u32(dsmem);
    const int gr = tid & 3;
    const int r0 = tid >> 2;

    float acc[2][8][4];
#pragma unroll
    for (int mt = 0; mt < 2; mt++)
#pragma unroll
        for (int nt = 0; nt < 8; nt++)
#pragma unroll
            for (int i = 0; i < 4; i++) acc[mt][nt][i] = 0.f;

    auto load_chunk = [&](int c, int stage) {
        int ac, bc;
        if (c < pchunks)          { ac = c;            bc = c; }
        else if (c < 2 * pchunks) { ac = c - pchunks;  bc = c; }
        else                      { ac = c - pchunks;  bc = c - 2 * pchunks; }
        uint32_t sa = sbase + stage * STAGE_BYTES;
        uint32_t sb = sa + 128 * PITCH;
        const __nv_bfloat16* As = Ag + ac * 32;
        const __nv_bfloat16* Bs = Bg + bc * 32;
#pragma unroll
        for (int p = 0; p < 2; p++) {
            int row = r0 + p * 64;
            uint32_t off = (uint32_t)row * PITCH + gr * 16u;
            CP_ASYNC16(sa + off, As + (size_t)row * lda + gr * 8);
            CP_ASYNC16(sb + off, Bs + (size_t)row * ldb + gr * 8);
        }
    };

    load_chunk(0, 0); CP_COMMIT();
    load_chunk(1, 1); CP_COMMIT();
    load_chunk(2, 2); CP_COMMIT();

    const int lrow = lane & 15;
    const int lcol = (lane >> 4) * 16;

    for (int c = 0; c < nchunk; ++c) {
        CP_WAIT2();
        __syncthreads();
        if (c + 3 < nchunk) load_chunk(c + 3, (c + 3) & 3);
        CP_COMMIT();

        const int s = c & 3;
        uint32_t sa = sbase + s * STAGE_BYTES;
        uint32_t sb = sa + 128 * PITCH;

#pragma unroll
        for (int ks = 0; ks < 2; ks++) {
            uint32_t afrag[2][4];
#pragma unroll
            for (int mt = 0; mt < 2; mt++) {
                uint32_t addr = sa + (uint32_t)(warp_m * 32 + mt * 16 + lrow) * PITCH
                              + ks * 32 + lcol;
                LDSM_X4(afrag[mt][0], afrag[mt][1], afrag[mt][2], afrag[mt][3], addr);
            }
            uint32_t bfrag[8][2];
#pragma unroll
            for (int nq = 0; nq < 4; nq++) {
                uint32_t t0, t1, t2, t3;
                uint32_t addr = sb + (uint32_t)(warp_n * 64 + nq * 16 + lrow) * PITCH
                              + ks * 32 + lcol;
                LDSM_X4(t0, t1, t2, t3, addr);
                bfrag[nq * 2 + 0][0] = t0; bfrag[nq * 2 + 0][1] = t2;
                bfrag[nq * 2 + 1][0] = t1; bfrag[nq * 2 + 1][1] = t3;
            }
#pragma unroll
            for (int mt = 0; mt < 2; mt++)
#pragma unroll
                for (int nt = 0; nt < 8; nt++)
                    MMA16816(acc[mt][nt], afrag[mt], bfrag[nt]);
        }
        __syncthreads();
    }

    // epilogue: store C; optional per-column max -> atomicMax
    const int crow = lane >> 2;
    const int ccol = (lane & 3) * 2;
#pragma unroll
    for (int mt = 0; mt < 2; mt++) {
#pragma unroll
        for (int nt = 0; nt < 8; nt++) {
            float* p = Cg + (size_t)(warp_m * 32 + mt * 16 + crow) * ldc
                         + warp_n * 64 + nt * 8 + ccol;
            *(float2*)p = make_float2(acc[mt][nt][0], acc[mt][nt][1]);
            *(float2*)(p + 8 * ldc) = make_float2(acc[mt][nt][2], acc[mt][nt][3]);
        }
    }
    if (maxArr) {
        unsigned* mrow = maxArr + b * NK + blockIdx.x * 128 + warp_n * 64;
#pragma unroll
        for (int nt = 0; nt < 8; nt++) {
            float c0 = fmaxf(fmaxf(acc[0][nt][0], acc[0][nt][2]),
                             fmaxf(acc[1][nt][0], acc[1][nt][2]));
            float c1 = fmaxf(fmaxf(acc[0][nt][1], acc[0][nt][3]),
                             fmaxf(acc[1][nt][1], acc[1][nt][3]));
#pragma unroll
            for (int off = 4; off < 32; off <<= 1) {
                c0 = fmaxf(c0, __shfl_xor_sync(0xffffffffu, c0, off));
                c1 = fmaxf(c1, __shfl_xor_sync(0xffffffffu, c1, off));
            }
            if (lane < 4) {
                atomicMax(&mrow[nt * 8 + (lane & 3) * 2],     fmax_flip(c0));
                atomicMax(&mrow[nt * 8 + (lane & 3) * 2 + 1], fmax_flip(c1));
            }
        }
    }
}

// ---------------------------------------------------------------------------
// Single-pass column softmax: read S once, write unnormalized E hi/lo and
// per-column 1/sum. Max comes precomputed from the QK epilogue.
// ---------------------------------------------------------------------------
__global__ __launch_bounds__(256) void col_softmax() {
    const int blk = blockIdx.x;
    const int b = blk / (NK / 32);
    const int kbase = (blk % (NK / 32)) * 32;
    const int tid = threadIdx.x;
    const int c = tid & 31;
    const int rg = tid >> 5;

    const float* S = gS + (size_t)b * NQ * NK + kbase;
    __nv_bfloat16* E = gEp + (size_t)b * NQ * 4096 + kbase;
    __shared__ float red[8][32];

    const float m = fmax_unflip(gMax[b * NK + kbase + c]);

    float sum = 0.f;
#pragma unroll 4
    for (int q = rg; q < NQ; q += 8) {
        float e = __expf(S[(size_t)q * NK + c] - m);
        __nv_bfloat16 hi = __float2bfloat16_rn(e);
        __nv_bfloat16 lo = __float2bfloat16_rn(e - __bfloat162float(hi));
        __nv_bfloat16* r = E + (size_t)q * 4096;
        r[c]        = hi;
        r[2048 + c] = lo;
        sum += e;
    }
    red[rg][c] = sum;
    __syncthreads();
    if (rg == 0) {
        float s = 0.f;
#pragma unroll
        for (int r = 0; r < 8; r++) s += red[r][c];
        gRecip[b * NK + kbase + c] = 1.0f / s;
    }
}

// ---------------------------------------------------------------------------
extern "C" void kernel_launch(void* const* d_in, const int* in_sizes, int n_in,
                              void* d_out, int out_size) {
    const float* Qm = (const float*)d_in[0];
    const float* Km = (const float*)d_in[1];
    const float* Vm = (const float*)d_in[2];
    float* Out = (float*)d_out;

    void *pQ, *pK, *pV, *pE, *pS, *pMax;
    cudaGetSymbolAddress(&pQ, gQp);
    cudaGetSymbolAddress(&pK, gKp);
    cudaGetSymbolAddress(&pV, gVT);
    cudaGetSymbolAddress(&pE, gEp);
    cudaGetSymbolAddress(&pS, gS);
    cudaGetSymbolAddress(&pMax, gMax);

    const int SMEM = 4 * STAGE_BYTES;   // 81920
    static bool attr_done = false;
    if (!attr_done) {
        cudaFuncSetAttribute(tc_gemm, cudaFuncAttributeMaxDynamicSharedMemorySize, SMEM);
        attr_done = true;
    }

    // prep Q'/K' (+ zero gMax)
    split_qk<<<dim3(NB * NQ, 2), 256>>>(Qm, Km);

    // S = Q' @ K'^T with fused column-max
    tc_gemm<<<dim3(NK / 128, NQ / 128, NB), 256, SMEM>>>(
        (const __nv_bfloat16*)pQ, (const __nv_bfloat16*)pK, (float*)pS,
        2048, 2048, NK, 32,
        (size_t)NQ * 2048, (size_t)NK * 2048, (size_t)NQ * NK,
        (unsigned*)pMax);

    // single-pass softmax -> E' (unnormalized) + gRecip
    col_softmax<<<NB * (NK / 32), 256>>>();

    // V transpose + recip scaling + split
    transpose_v<<<dim3(ND / 32, NK / 32, NB), 256>>>(Vm);

    // Out = E' @ VT'^T
    tc_gemm<<<dim3(ND / 128, NQ / 128, NB), 256, SMEM>>>(
        (const __nv_bfloat16*)pE, (const __nv_bfloat16*)pV, Out,
        4096, 4096, ND, 64,
        (size_t)NQ * 4096, (size_t)ND * 4096, (size_t)NQ * ND,
        (unsigned*)nullptr);
}